// round 3
// baseline (speedup 1.0000x reference)
#include <cuda_runtime.h>

// ---------------------------------------------------------------------------
// GCN 2-layer encoder (pull-based, CSR built per call).
//   deg_i = indeg(dst) + 1 ; dinv = rsqrt(deg)
//   layer(x,W,b): h = x @ W^T ; out_i = dinv_i*(sum_{j->i} dinv_j h_j + dinv_i h_i) + b
//   leaky_relu(0.01) after each layer
// edge_index dtype (int32 vs int64) detected at runtime — JAX default x64=off
// means the "int64" reference array is most likely materialized as int32.
// ---------------------------------------------------------------------------

#define N_NODES 100000
#define N_EDGES 1600000
#define FDIM    128
#define SCAN_B  1024
#define SCAN_NB ((N_NODES + SCAN_B - 1) / SCAN_B)   // 98

__device__ int   g_is64;
__device__ int   g_deg[N_NODES];
__device__ int   g_pos[N_NODES];
__device__ int   g_off[N_NODES + 1];
__device__ int   g_bsum[SCAN_NB];
__device__ float g_dinv[N_NODES];
__device__ int   g_csr[N_EDGES];
__device__ float g_h[(size_t)N_NODES * FDIM];   // GEMM output (per layer)
__device__ float g_y[(size_t)N_NODES * FDIM];   // layer-1 activation

// ---------------- dtype detection ----------------
// int64 nonneg values < 2^31: every odd 32-bit word is 0. int32 node ids:
// odd words are random ids, all-zero has probability ~(1e-5)^256.
__global__ void detect_kernel(const unsigned int* __restrict__ w) {
    int zeros = 0;
    for (int k = 0; k < 256; k++)
        if (w[2 * k + 1] == 0u) zeros++;
    g_is64 = (zeros == 256) ? 1 : 0;
}

__device__ __forceinline__ int edge_at(const void* ei, long long idx, int n) {
    long long v = g_is64 ? ((const long long*)ei)[idx]
                         : (long long)((const int*)ei)[idx];
    int i = (int)v;
    if (i < 0) i = 0;
    if (i >= n) i = n - 1;
    return i;
}

// ---------------- CSR build ----------------

__global__ void zero_kernel(int n) {
    int i = blockIdx.x * blockDim.x + threadIdx.x;
    if (i < n) { g_deg[i] = 0; g_pos[i] = 0; }
}

__global__ void deg_kernel(const void* __restrict__ ei, int E, int n) {
    int e = blockIdx.x * blockDim.x + threadIdx.x;
    if (e < E) {
        int d = edge_at(ei, (long long)E + e, n);   // dst row
        atomicAdd(&g_deg[d], 1);
    }
}

__global__ void dinv_kernel(int n) {
    int i = blockIdx.x * blockDim.x + threadIdx.x;
    if (i < n) g_dinv[i] = rsqrtf((float)g_deg[i] + 1.0f);
}

// per-block exclusive scan of counts -> g_off (local), block totals -> g_bsum
__global__ void scan1_kernel(int n) {
    __shared__ int s[SCAN_B];
    int t = threadIdx.x;
    int i = blockIdx.x * SCAN_B + t;
    int v = (i < n) ? g_deg[i] : 0;
    s[t] = v;
    __syncthreads();
    for (int o = 1; o < SCAN_B; o <<= 1) {
        int x = (t >= o) ? s[t - o] : 0;
        __syncthreads();
        s[t] += x;
        __syncthreads();
    }
    if (i < n) g_off[i] = s[t] - v;          // exclusive within block
    if (t == SCAN_B - 1) g_bsum[blockIdx.x] = s[t];
}

__global__ void scan2_kernel(int nb, int n, int E) {
    int run = 0;
    for (int b = 0; b < nb; b++) { int v = g_bsum[b]; g_bsum[b] = run; run += v; }
    g_off[n] = E;
}

__global__ void scan3_kernel(int n) {
    int i = blockIdx.x * SCAN_B + threadIdx.x;
    if (i < n) g_off[i] += g_bsum[blockIdx.x];
}

__global__ void scatter_kernel(const void* __restrict__ ei, int E, int n) {
    int e = blockIdx.x * blockDim.x + threadIdx.x;
    if (e < E) {
        int s = edge_at(ei, e, n);                 // src row
        int d = edge_at(ei, (long long)E + e, n);  // dst row
        int p = g_off[d] + atomicAdd(&g_pos[d], 1);
        g_csr[p] = s;
    }
}

// ---------------- GEMM: g_h[M,128] = A[M,128] @ W^T  (A = arg or g_y) -------

#define BM 128
#define BK 16
#define PAD 132   // BM + 4 padding, multiple of 4 for float4 LDS

__global__ __launch_bounds__(256, 2)
void gemm_xwT_kernel(const float* __restrict__ Aopt, const float* __restrict__ W,
                     int M) {
    const float* A = Aopt ? Aopt : g_y;
    __shared__ float As[BK][PAD];
    __shared__ float Ws[BK][PAD];
    int tid = threadIdx.x;
    int row0 = blockIdx.x * BM;
    int tx = tid & 15, ty = tid >> 4;
    int m0 = ty * 8, n0 = tx * 8;
    float acc[8][8];
#pragma unroll
    for (int i = 0; i < 8; i++)
#pragma unroll
        for (int j = 0; j < 8; j++) acc[i][j] = 0.0f;

    int lr = tid >> 1;           // 0..127: row within tile
    int lk = (tid & 1) * 8;      // 0 or 8: k offset

    for (int k0 = 0; k0 < FDIM; k0 += BK) {
        float4 a0 = {0,0,0,0}, a1 = {0,0,0,0};
        int ar = row0 + lr;
        if (ar < M) {
            const float4* Ap = (const float4*)(A + (size_t)ar * FDIM + k0 + lk);
            a0 = Ap[0]; a1 = Ap[1];
        }
        const float4* Wp = (const float4*)(W + (size_t)lr * FDIM + k0 + lk);
        float4 w0 = Wp[0], w1 = Wp[1];
#pragma unroll
        for (int q = 0; q < 4; q++) {
            As[lk + q][lr]     = ((const float*)&a0)[q];
            As[lk + 4 + q][lr] = ((const float*)&a1)[q];
            Ws[lk + q][lr]     = ((const float*)&w0)[q];
            Ws[lk + 4 + q][lr] = ((const float*)&w1)[q];
        }
        __syncthreads();
#pragma unroll
        for (int k = 0; k < BK; k++) {
            float a[8], b[8];
            *(float4*)&a[0] = *(const float4*)&As[k][m0];
            *(float4*)&a[4] = *(const float4*)&As[k][m0 + 4];
            *(float4*)&b[0] = *(const float4*)&Ws[k][n0];
            *(float4*)&b[4] = *(const float4*)&Ws[k][n0 + 4];
#pragma unroll
            for (int i = 0; i < 8; i++)
#pragma unroll
                for (int j = 0; j < 8; j++) acc[i][j] += a[i] * b[j];
        }
        __syncthreads();
    }
#pragma unroll
    for (int i = 0; i < 8; i++) {
        int r = row0 + m0 + i;
        if (r < M) {
            float4 o0, o1;
            o0.x = acc[i][0]; o0.y = acc[i][1]; o0.z = acc[i][2]; o0.w = acc[i][3];
            o1.x = acc[i][4]; o1.y = acc[i][5]; o1.z = acc[i][6]; o1.w = acc[i][7];
            *(float4*)(g_h + (size_t)r * FDIM + n0)     = o0;
            *(float4*)(g_h + (size_t)r * FDIM + n0 + 4) = o1;
        }
    }
}

// ---------------- Pull aggregation + bias + leaky_relu ----------------
// one warp per node; lane holds 4 features (float4); reads g_h, writes
// outopt (or g_y when outopt == nullptr).

__global__ __launch_bounds__(256)
void agg_kernel(const float* __restrict__ bias, float* __restrict__ outopt, int n) {
    float4* out4 = outopt ? (float4*)outopt : (float4*)g_y;
    const float4* h4 = (const float4*)g_h;
    int gtid = blockIdx.x * blockDim.x + threadIdx.x;
    int node = gtid >> 5;
    int lane = threadIdx.x & 31;
    if (node >= n) return;

    float di  = g_dinv[node];
    int beg = g_off[node], end = g_off[node + 1];
    float4 acc = {0.f, 0.f, 0.f, 0.f};
    for (int e = beg; e < end; e++) {
        int j = g_csr[e];
        float dj = __ldg(&g_dinv[j]);
        float4 hj = __ldg(&h4[(size_t)j * 32 + lane]);
        acc.x += dj * hj.x; acc.y += dj * hj.y;
        acc.z += dj * hj.z; acc.w += dj * hj.w;
    }
    float4 hi = __ldg(&h4[(size_t)node * 32 + lane]);
    float4 bb = __ldg(((const float4*)bias) + lane);
    float4 o;
    o.x = di * (acc.x + di * hi.x) + bb.x;
    o.y = di * (acc.y + di * hi.y) + bb.y;
    o.z = di * (acc.z + di * hi.z) + bb.z;
    o.w = di * (acc.w + di * hi.w) + bb.w;
    o.x = o.x > 0.f ? o.x : 0.01f * o.x;
    o.y = o.y > 0.f ? o.y : 0.01f * o.y;
    o.z = o.z > 0.f ? o.z : 0.01f * o.z;
    o.w = o.w > 0.f ? o.w : 0.01f * o.w;
    out4[(size_t)node * 32 + lane] = o;
}

// ---------------- launch ----------------

extern "C" void kernel_launch(void* const* d_in, const int* in_sizes, int n_in,
                              void* d_out, int out_size) {
    const float* x  = (const float*)d_in[0];
    const void*  ei = d_in[1];
    const float* W1 = (const float*)d_in[2];
    const float* b1 = (const float*)d_in[3];
    const float* W2 = (const float*)d_in[4];
    const float* b2 = (const float*)d_in[5];
    float*       out = (float*)d_out;

    int N = in_sizes[0] / FDIM;        // 100000
    int E = in_sizes[1] / 2;           // 1600000

    int nB = (N + 255) / 256;
    int eB = (E + 255) / 256;
    int gemmB = (N + BM - 1) / BM;
    int aggB  = (N * 32 + 255) / 256;

    // CSR build
    detect_kernel<<<1, 1>>>((const unsigned int*)ei);
    zero_kernel<<<nB, 256>>>(N);
    deg_kernel<<<eB, 256>>>(ei, E, N);
    dinv_kernel<<<nB, 256>>>(N);
    scan1_kernel<<<SCAN_NB, SCAN_B>>>(N);
    scan2_kernel<<<1, 1>>>(SCAN_NB, N, E);
    scan3_kernel<<<SCAN_NB, SCAN_B>>>(N);
    scatter_kernel<<<eB, 256>>>(ei, E, N);

    // layer 1: h = x@W1^T ; y = agg(h)+b1, lrelu
    gemm_xwT_kernel<<<gemmB, 256>>>(x, W1, N);
    agg_kernel<<<aggB, 256>>>(b1, nullptr, N);
    // layer 2: h = y@W2^T ; out = agg(h)+b2, lrelu
    gemm_xwT_kernel<<<gemmB, 256>>>(nullptr, W2, N);
    agg_kernel<<<aggB, 256>>>(b2, out, N);
}

// round 5
// speedup vs baseline: 1.0634x; 1.0634x over previous
#include <cuda_runtime.h>
#include <cuda_bf16.h>
#include <cstdint>

// ---------------------------------------------------------------------------
// GCN 2-layer encoder. CSR built per call; pull-based aggregation; GEMM via
// mma.sync bf16 3-term split (Ah*Wh + Ah*Wl + Al*Wh, fp32 accumulate).
// (tcgen05 is unavailable: harness compiles for compute_103, not 103a.)
// ---------------------------------------------------------------------------

#define N_NODES 100000
#define N_EDGES 1600000
#define FDIM    128
#define SCAN_B  1024
#define SCAN_NB ((N_NODES + SCAN_B - 1) / SCAN_B)   // 98

__device__ int   g_is64;
__device__ int   g_deg[N_NODES];
__device__ int   g_pos[N_NODES];
__device__ int   g_off[N_NODES + 1];
__device__ int   g_bsum[SCAN_NB];
__device__ float g_dinv[N_NODES];
__device__ int   g_csr[N_EDGES];
__device__ float g_h[(size_t)N_NODES * FDIM];   // GEMM output (per layer)
__device__ float g_y[(size_t)N_NODES * FDIM];   // layer-1 activation

// ---------------- dtype detection ----------------
__global__ void detect_kernel(const unsigned int* __restrict__ w) {
    int zeros = 0;
    for (int k = 0; k < 256; k++)
        if (w[2 * k + 1] == 0u) zeros++;
    g_is64 = (zeros == 256) ? 1 : 0;
}

__device__ __forceinline__ int edge_at(const void* ei, long long idx, int n) {
    long long v = g_is64 ? ((const long long*)ei)[idx]
                         : (long long)((const int*)ei)[idx];
    int i = (int)v;
    if (i < 0) i = 0;
    if (i >= n) i = n - 1;
    return i;
}

// ---------------- CSR build ----------------

__global__ void zero_kernel(int n) {
    int i = blockIdx.x * blockDim.x + threadIdx.x;
    if (i < n) { g_deg[i] = 0; g_pos[i] = 0; }
}

__global__ void deg_kernel(const void* __restrict__ ei, int E, int n) {
    int e = blockIdx.x * blockDim.x + threadIdx.x;
    if (e < E) atomicAdd(&g_deg[edge_at(ei, (long long)E + e, n)], 1);
}

__global__ void dinv_kernel(int n) {
    int i = blockIdx.x * blockDim.x + threadIdx.x;
    if (i < n) g_dinv[i] = rsqrtf((float)g_deg[i] + 1.0f);
}

__global__ void scan1_kernel(int n) {
    __shared__ int s[SCAN_B];
    int t = threadIdx.x;
    int i = blockIdx.x * SCAN_B + t;
    int v = (i < n) ? g_deg[i] : 0;
    s[t] = v;
    __syncthreads();
    for (int o = 1; o < SCAN_B; o <<= 1) {
        int x = (t >= o) ? s[t - o] : 0;
        __syncthreads();
        s[t] += x;
        __syncthreads();
    }
    if (i < n) g_off[i] = s[t] - v;
    if (t == SCAN_B - 1) g_bsum[blockIdx.x] = s[t];
}

__global__ void scan2_kernel(int nb, int n, int E) {
    int run = 0;
    for (int b = 0; b < nb; b++) { int v = g_bsum[b]; g_bsum[b] = run; run += v; }
    g_off[n] = E;
}

__global__ void scan3_kernel(int n) {
    int i = blockIdx.x * SCAN_B + threadIdx.x;
    if (i < n) g_off[i] += g_bsum[blockIdx.x];
}

__global__ void scatter_kernel(const void* __restrict__ ei, int E, int n) {
    int e = blockIdx.x * blockDim.x + threadIdx.x;
    if (e < E) {
        int s = edge_at(ei, e, n);
        int d = edge_at(ei, (long long)E + e, n);
        int p = g_off[d] + atomicAdd(&g_pos[d], 1);
        g_csr[p] = s;
    }
}

// ---------------- mma.sync bf16x3 GEMM: g_h[M,128] = A[M,128] @ W^T --------
// smem tiles: rows padded to 136 bf16 (272 B = 17*16B) so ldmatrix row
// addresses rotate through banks (conflict-free without swizzle).

#define TROWB 272                        // bytes per padded tile row
#define TSZ   (128 * TROWB)              // 34816 B per tile
#define AHI_O 0
#define ALO_O (TSZ)
#define WHI_O (2 * TSZ)
#define WLO_O (3 * TSZ)
#define SM_TOT (4 * TSZ)                 // 139264 B dynamic smem

__device__ __forceinline__ uint32_t smem_u32(const void* p) {
    uint32_t a;
    asm("{ .reg .u64 t; cvta.to.shared.u64 t, %1; cvt.u32.u64 %0, t; }"
        : "=r"(a) : "l"(p));
    return a;
}

__device__ __forceinline__ uint32_t pack_bf2(__nv_bfloat16 a, __nv_bfloat16 b) {
    return (uint32_t)__bfloat16_as_ushort(a) | ((uint32_t)__bfloat16_as_ushort(b) << 16);
}

__device__ __forceinline__ void cvt_store(char* smem, int hi_off, int lo_off,
                                          int r, int c4, float4 v) {
    __nv_bfloat16 h0 = __float2bfloat16_rn(v.x);
    __nv_bfloat16 h1 = __float2bfloat16_rn(v.y);
    __nv_bfloat16 h2 = __float2bfloat16_rn(v.z);
    __nv_bfloat16 h3 = __float2bfloat16_rn(v.w);
    __nv_bfloat16 l0 = __float2bfloat16_rn(v.x - __bfloat162float(h0));
    __nv_bfloat16 l1 = __float2bfloat16_rn(v.y - __bfloat162float(h1));
    __nv_bfloat16 l2 = __float2bfloat16_rn(v.z - __bfloat162float(h2));
    __nv_bfloat16 l3 = __float2bfloat16_rn(v.w - __bfloat162float(h3));
    int off = r * TROWB + c4 * 2;        // 8B aligned
    uint2 hp; hp.x = pack_bf2(h0, h1); hp.y = pack_bf2(h2, h3);
    uint2 lp; lp.x = pack_bf2(l0, l1); lp.y = pack_bf2(l2, l3);
    *(uint2*)(smem + hi_off + off) = hp;
    *(uint2*)(smem + lo_off + off) = lp;
}

__device__ __forceinline__ void ldm_x4(uint32_t* r, uint32_t addr) {
    asm volatile("ldmatrix.sync.aligned.m8n8.x4.shared.b16 {%0,%1,%2,%3}, [%4];"
                 : "=r"(r[0]), "=r"(r[1]), "=r"(r[2]), "=r"(r[3]) : "r"(addr));
}

__device__ __forceinline__ void mma_bf16(float* c, const uint32_t* a,
                                         uint32_t b0, uint32_t b1) {
    asm volatile(
        "mma.sync.aligned.m16n8k16.row.col.f32.bf16.bf16.f32 "
        "{%0,%1,%2,%3}, {%4,%5,%6,%7}, {%8,%9}, {%0,%1,%2,%3};"
        : "+f"(c[0]), "+f"(c[1]), "+f"(c[2]), "+f"(c[3])
        : "r"(a[0]), "r"(a[1]), "r"(a[2]), "r"(a[3]), "r"(b0), "r"(b1));
}

__global__ __launch_bounds__(256, 1)
void gemm_mma_kernel(const float* __restrict__ Aopt, const float* __restrict__ W,
                     int M) {
    extern __shared__ char smem[];
    const float* A = Aopt ? Aopt : g_y;
    int tid = threadIdx.x;
    int wid = tid >> 5;
    int lane = tid & 31;
    int row0 = blockIdx.x * 128;
    int trows = (row0 + 128 <= M) ? 128 : (M - row0);

    // load + split-convert A (guarded) and W tiles into padded smem
    for (int idx = tid; idx < 128 * 32; idx += 256) {
        int r = idx >> 5;
        int c4 = (idx & 31) << 2;
        float4 v = {0.f, 0.f, 0.f, 0.f};
        if (r < trows) v = *(const float4*)(A + (size_t)(row0 + r) * FDIM + c4);
        cvt_store(smem, AHI_O, ALO_O, r, c4, v);
        float4 wv = *(const float4*)(W + (size_t)r * FDIM + c4);
        cvt_store(smem, WHI_O, WLO_O, r, c4, wv);
    }
    __syncthreads();

    uint32_t sbase = smem_u32(smem);
    int warpM = wid & 3;                 // 4 -> 128 rows
    int warpN = wid >> 2;                // 2 -> 128 cols

    float acc[2][8][4];
#pragma unroll
    for (int mt = 0; mt < 2; mt++)
#pragma unroll
        for (int nt = 0; nt < 8; nt++)
#pragma unroll
            for (int q = 0; q < 4; q++) acc[mt][nt][q] = 0.f;

    // per-lane ldmatrix base offsets (within a tile)
    // A x4: matrices {m0-7 k0, m8-15 k0, m0-7 k8, m8-15 k8}
    uint32_t aoff = (uint32_t)((warpM * 32 + (lane & 15)) * TROWB + ((lane >> 4) * 8) * 2);
    // B x4: g=lane>>3 -> {nt0 k0, nt0 k8, nt1 k0, nt1 k8}; npair covers 16 cols
    int g = lane >> 3;
    uint32_t boff = (uint32_t)((warpN * 64 + (g >> 1) * 8 + (lane & 7)) * TROWB + (g & 1) * 16);

#pragma unroll
    for (int t = 0; t < 3; t++) {
        uint32_t abase = sbase + (t == 2 ? ALO_O : AHI_O) + aoff;
        uint32_t bbase = sbase + (t == 1 ? WLO_O : WHI_O) + boff;
#pragma unroll
        for (int ks = 0; ks < 8; ks++) {
            uint32_t af[2][4], bf[4][4];
            ldm_x4(af[0], abase + ks * 32);
            ldm_x4(af[1], abase + 16 * TROWB + ks * 32);
#pragma unroll
            for (int np = 0; np < 4; np++)
                ldm_x4(bf[np], bbase + np * 16 * TROWB + ks * 32);
#pragma unroll
            for (int mt = 0; mt < 2; mt++)
#pragma unroll
                for (int nt = 0; nt < 8; nt++)
                    mma_bf16(acc[mt][nt], af[mt],
                             bf[nt >> 1][(nt & 1) * 2], bf[nt >> 1][(nt & 1) * 2 + 1]);
        }
    }

    // epilogue: C fragment thread l: rows l/4, l/4+8; cols 2*(l%4)+{0,1}
    int crow = warpM * 32 + (lane >> 2);
    int ccol = warpN * 64 + (lane & 3) * 2;
#pragma unroll
    for (int mt = 0; mt < 2; mt++) {
#pragma unroll
        for (int nt = 0; nt < 8; nt++) {
            int r0 = row0 + crow + mt * 16;
            int c = ccol + nt * 8;
            if (r0 < M) {
                float2 v0 = {acc[mt][nt][0], acc[mt][nt][1]};
                *(float2*)(g_h + (size_t)r0 * FDIM + c) = v0;
            }
            if (r0 + 8 < M) {
                float2 v1 = {acc[mt][nt][2], acc[mt][nt][3]};
                *(float2*)(g_h + (size_t)(r0 + 8) * FDIM + c) = v1;
            }
        }
    }
}

// ---------------- Pull aggregation + bias + leaky_relu ----------------

__global__ __launch_bounds__(256)
void agg_kernel(const float* __restrict__ bias, float* __restrict__ outopt, int n) {
    float4* out4 = outopt ? (float4*)outopt : (float4*)g_y;
    const float4* h4 = (const float4*)g_h;
    int gtid = blockIdx.x * blockDim.x + threadIdx.x;
    int node = gtid >> 5;
    int lane = threadIdx.x & 31;
    if (node >= n) return;

    float di  = g_dinv[node];
    int beg = g_off[node], end = g_off[node + 1];
    float4 acc = {0.f, 0.f, 0.f, 0.f};
    for (int e = beg; e < end; e++) {
        int j = g_csr[e];
        float dj = __ldg(&g_dinv[j]);
        float4 hj = __ldg(&h4[(size_t)j * 32 + lane]);
        acc.x += dj * hj.x; acc.y += dj * hj.y;
        acc.z += dj * hj.z; acc.w += dj * hj.w;
    }
    float4 hi = __ldg(&h4[(size_t)node * 32 + lane]);
    float4 bb = __ldg(((const float4*)bias) + lane);
    float4 o;
    o.x = di * (acc.x + di * hi.x) + bb.x;
    o.y = di * (acc.y + di * hi.y) + bb.y;
    o.z = di * (acc.z + di * hi.z) + bb.z;
    o.w = di * (acc.w + di * hi.w) + bb.w;
    o.x = o.x > 0.f ? o.x : 0.01f * o.x;
    o.y = o.y > 0.f ? o.y : 0.01f * o.y;
    o.z = o.z > 0.f ? o.z : 0.01f * o.z;
    o.w = o.w > 0.f ? o.w : 0.01f * o.w;
    out4[(size_t)node * 32 + lane] = o;
}

// ---------------- launch ----------------

extern "C" void kernel_launch(void* const* d_in, const int* in_sizes, int n_in,
                              void* d_out, int out_size) {
    const float* x  = (const float*)d_in[0];
    const void*  ei = d_in[1];
    const float* W1 = (const float*)d_in[2];
    const float* b1 = (const float*)d_in[3];
    const float* W2 = (const float*)d_in[4];
    const float* b2 = (const float*)d_in[5];
    float*       out = (float*)d_out;

    int N = in_sizes[0] / FDIM;        // 100000
    int E = in_sizes[1] / 2;           // 1600000

    int nB = (N + 255) / 256;
    int eB = (E + 255) / 256;
    int gemmB = (N + 127) / 128;
    int aggB  = (N * 32 + 255) / 256;

    cudaFuncSetAttribute(gemm_mma_kernel,
                         cudaFuncAttributeMaxDynamicSharedMemorySize, SM_TOT);

    // CSR build
    detect_kernel<<<1, 1>>>((const unsigned int*)ei);
    zero_kernel<<<nB, 256>>>(N);
    deg_kernel<<<eB, 256>>>(ei, E, N);
    dinv_kernel<<<nB, 256>>>(N);
    scan1_kernel<<<SCAN_NB, SCAN_B>>>(N);
    scan2_kernel<<<1, 1>>>(SCAN_NB, N, E);
    scan3_kernel<<<SCAN_NB, SCAN_B>>>(N);
    scatter_kernel<<<eB, 256>>>(ei, E, N);

    // layer 1: h = x@W1^T ; y = agg(h)+b1, lrelu
    gemm_mma_kernel<<<gemmB, 256, SM_TOT>>>(x, W1, N);
    agg_kernel<<<aggB, 256>>>(b1, nullptr, N);
    // layer 2: h = y@W2^T ; out = agg(h)+b2, lrelu
    gemm_mma_kernel<<<gemmB, 256, SM_TOT>>>(nullptr, W2, N);
    agg_kernel<<<aggB, 256>>>(b2, out, N);
}

// round 6
// speedup vs baseline: 1.2015x; 1.1299x over previous
#include <cuda_runtime.h>
#include <cuda_bf16.h>
#include <cuda_fp16.h>
#include <cstdint>

// ---------------------------------------------------------------------------
// GCN 2-layer encoder. CSR built per call; pull-based aggregation over an
// fp16 copy of h (halves gather traffic; error ~5e-4 rel, threshold 1e-3);
// GEMM via mma.sync bf16 3-term split (fp32 accumulate).
// ---------------------------------------------------------------------------

#define N_NODES 100000
#define N_EDGES 1600000
#define FDIM    128
#define SCAN_B  1024
#define SCAN_NB ((N_NODES + SCAN_B - 1) / SCAN_B)   // 98

__device__ int    g_is64;
__device__ int    g_deg[N_NODES];
__device__ int    g_pos[N_NODES];
__device__ int    g_off[N_NODES + 1];
__device__ int    g_bsum[SCAN_NB];
__device__ float  g_dinv[N_NODES];
__device__ int    g_csr[N_EDGES];
__device__ __half g_h[(size_t)N_NODES * FDIM];   // GEMM output, fp16 (per layer)
__device__ float  g_y[(size_t)N_NODES * FDIM];   // layer-1 activation (fp32)

// ---------------- dtype detection (parallel) ----------------
__global__ void detect_kernel(const unsigned int* __restrict__ w) {
    int z = (w[2 * threadIdx.x + 1] == 0u) ? 1 : 0;
    int total = __syncthreads_count(z);
    if (threadIdx.x == 0) g_is64 = (total == 256) ? 1 : 0;
}

__device__ __forceinline__ int edge_at(const void* ei, long long idx, int n) {
    long long v = g_is64 ? ((const long long*)ei)[idx]
                         : (long long)((const int*)ei)[idx];
    int i = (int)v;
    if (i < 0) i = 0;
    if (i >= n) i = n - 1;
    return i;
}

// ---------------- CSR build ----------------

__global__ void zero_kernel(int n) {
    int i = blockIdx.x * blockDim.x + threadIdx.x;
    if (i < n) { g_deg[i] = 0; g_pos[i] = 0; }
}

__global__ void deg_kernel(const void* __restrict__ ei, int E, int n) {
    int e = blockIdx.x * blockDim.x + threadIdx.x;
    if (e < E) atomicAdd(&g_deg[edge_at(ei, (long long)E + e, n)], 1);
}

__global__ void dinv_kernel(int n) {
    int i = blockIdx.x * blockDim.x + threadIdx.x;
    if (i < n) g_dinv[i] = rsqrtf((float)g_deg[i] + 1.0f);
}

__global__ void scan1_kernel(int n) {
    __shared__ int s[SCAN_B];
    int t = threadIdx.x;
    int i = blockIdx.x * SCAN_B + t;
    int v = (i < n) ? g_deg[i] : 0;
    s[t] = v;
    __syncthreads();
    for (int o = 1; o < SCAN_B; o <<= 1) {
        int x = (t >= o) ? s[t - o] : 0;
        __syncthreads();
        s[t] += x;
        __syncthreads();
    }
    if (i < n) g_off[i] = s[t] - v;
    if (t == SCAN_B - 1) g_bsum[blockIdx.x] = s[t];
}

__global__ void scan2_kernel(int nb, int n, int E) {
    int run = 0;
    for (int b = 0; b < nb; b++) { int v = g_bsum[b]; g_bsum[b] = run; run += v; }
    g_off[n] = E;
}

__global__ void scan3_kernel(int n) {
    int i = blockIdx.x * SCAN_B + threadIdx.x;
    if (i < n) g_off[i] += g_bsum[blockIdx.x];
}

__global__ void scatter_kernel(const void* __restrict__ ei, int E, int n) {
    int e = blockIdx.x * blockDim.x + threadIdx.x;
    if (e < E) {
        int s = edge_at(ei, e, n);
        int d = edge_at(ei, (long long)E + e, n);
        int p = g_off[d] + atomicAdd(&g_pos[d], 1);
        g_csr[p] = s;
    }
}

// ---------------- mma.sync bf16x3 GEMM: g_h[M,128](fp16) = A[M,128] @ W^T --
// smem tiles: rows padded to 136 bf16 (272 B = 17*16B): ldmatrix row
// addresses rotate banks, conflict-free without swizzle.

#define TROWB 272
#define TSZ   (128 * TROWB)
#define AHI_O 0
#define ALO_O (TSZ)
#define WHI_O (2 * TSZ)
#define WLO_O (3 * TSZ)
#define SM_TOT (4 * TSZ)                 // 139264 B dynamic smem

__device__ __forceinline__ uint32_t smem_u32(const void* p) {
    uint32_t a;
    asm("{ .reg .u64 t; cvta.to.shared.u64 t, %1; cvt.u32.u64 %0, t; }"
        : "=r"(a) : "l"(p));
    return a;
}

__device__ __forceinline__ uint32_t pack_bf2(__nv_bfloat16 a, __nv_bfloat16 b) {
    return (uint32_t)__bfloat16_as_ushort(a) | ((uint32_t)__bfloat16_as_ushort(b) << 16);
}

__device__ __forceinline__ void cvt_store(char* smem, int hi_off, int lo_off,
                                          int r, int c4, float4 v) {
    __nv_bfloat16 h0 = __float2bfloat16_rn(v.x);
    __nv_bfloat16 h1 = __float2bfloat16_rn(v.y);
    __nv_bfloat16 h2 = __float2bfloat16_rn(v.z);
    __nv_bfloat16 h3 = __float2bfloat16_rn(v.w);
    __nv_bfloat16 l0 = __float2bfloat16_rn(v.x - __bfloat162float(h0));
    __nv_bfloat16 l1 = __float2bfloat16_rn(v.y - __bfloat162float(h1));
    __nv_bfloat16 l2 = __float2bfloat16_rn(v.z - __bfloat162float(h2));
    __nv_bfloat16 l3 = __float2bfloat16_rn(v.w - __bfloat162float(h3));
    int off = r * TROWB + c4 * 2;
    uint2 hp; hp.x = pack_bf2(h0, h1); hp.y = pack_bf2(h2, h3);
    uint2 lp; lp.x = pack_bf2(l0, l1); lp.y = pack_bf2(l2, l3);
    *(uint2*)(smem + hi_off + off) = hp;
    *(uint2*)(smem + lo_off + off) = lp;
}

__device__ __forceinline__ void ldm_x4(uint32_t* r, uint32_t addr) {
    asm volatile("ldmatrix.sync.aligned.m8n8.x4.shared.b16 {%0,%1,%2,%3}, [%4];"
                 : "=r"(r[0]), "=r"(r[1]), "=r"(r[2]), "=r"(r[3]) : "r"(addr));
}

__device__ __forceinline__ void mma_bf16(float* c, const uint32_t* a,
                                         uint32_t b0, uint32_t b1) {
    asm volatile(
        "mma.sync.aligned.m16n8k16.row.col.f32.bf16.bf16.f32 "
        "{%0,%1,%2,%3}, {%4,%5,%6,%7}, {%8,%9}, {%0,%1,%2,%3};"
        : "+f"(c[0]), "+f"(c[1]), "+f"(c[2]), "+f"(c[3])
        : "r"(a[0]), "r"(a[1]), "r"(a[2]), "r"(a[3]), "r"(b0), "r"(b1));
}

__global__ __launch_bounds__(256, 1)
void gemm_mma_kernel(const float* __restrict__ Aopt, const float* __restrict__ W,
                     int M) {
    extern __shared__ char smem[];
    const float* A = Aopt ? Aopt : g_y;
    int tid = threadIdx.x;
    int wid = tid >> 5;
    int lane = tid & 31;
    int row0 = blockIdx.x * 128;
    int trows = (row0 + 128 <= M) ? 128 : (M - row0);

    for (int idx = tid; idx < 128 * 32; idx += 256) {
        int r = idx >> 5;
        int c4 = (idx & 31) << 2;
        float4 v = {0.f, 0.f, 0.f, 0.f};
        if (r < trows) v = *(const float4*)(A + (size_t)(row0 + r) * FDIM + c4);
        cvt_store(smem, AHI_O, ALO_O, r, c4, v);
        float4 wv = *(const float4*)(W + (size_t)r * FDIM + c4);
        cvt_store(smem, WHI_O, WLO_O, r, c4, wv);
    }
    __syncthreads();

    uint32_t sbase = smem_u32(smem);
    int warpM = wid & 3;
    int warpN = wid >> 2;

    float acc[2][8][4];
#pragma unroll
    for (int mt = 0; mt < 2; mt++)
#pragma unroll
        for (int nt = 0; nt < 8; nt++)
#pragma unroll
            for (int q = 0; q < 4; q++) acc[mt][nt][q] = 0.f;

    uint32_t aoff = (uint32_t)((warpM * 32 + (lane & 15)) * TROWB + ((lane >> 4) * 8) * 2);
    int g = lane >> 3;
    uint32_t boff = (uint32_t)((warpN * 64 + (g >> 1) * 8 + (lane & 7)) * TROWB + (g & 1) * 16);

#pragma unroll
    for (int t = 0; t < 3; t++) {
        uint32_t abase = sbase + (t == 2 ? ALO_O : AHI_O) + aoff;
        uint32_t bbase = sbase + (t == 1 ? WLO_O : WHI_O) + boff;
#pragma unroll
        for (int ks = 0; ks < 8; ks++) {
            uint32_t af[2][4], bf[4][4];
            ldm_x4(af[0], abase + ks * 32);
            ldm_x4(af[1], abase + 16 * TROWB + ks * 32);
#pragma unroll
            for (int np = 0; np < 4; np++)
                ldm_x4(bf[np], bbase + np * 16 * TROWB + ks * 32);
#pragma unroll
            for (int mt = 0; mt < 2; mt++)
#pragma unroll
                for (int nt = 0; nt < 8; nt++)
                    mma_bf16(acc[mt][nt], af[mt],
                             bf[nt >> 1][(nt & 1) * 2], bf[nt >> 1][(nt & 1) * 2 + 1]);
        }
    }

    // epilogue -> fp16 g_h. C frag: rows l/4, l/4+8; cols 2*(l%4)+{0,1}
    int crow = warpM * 32 + (lane >> 2);
    int ccol = warpN * 64 + (lane & 3) * 2;
#pragma unroll
    for (int mt = 0; mt < 2; mt++) {
#pragma unroll
        for (int nt = 0; nt < 8; nt++) {
            int r0 = row0 + crow + mt * 16;
            int c = ccol + nt * 8;
            if (r0 < M) {
                float2 v0 = {acc[mt][nt][0], acc[mt][nt][1]};
                *(__half2*)(g_h + (size_t)r0 * FDIM + c) = __float22half2_rn(v0);
            }
            if (r0 + 8 < M) {
                float2 v1 = {acc[mt][nt][2], acc[mt][nt][3]};
                *(__half2*)(g_h + (size_t)(r0 + 8) * FDIM + c) = __float22half2_rn(v1);
            }
        }
    }
}

// ---------------- Pull aggregation + bias + leaky_relu ----------------
// one warp per node; lane covers features lane*4..lane*4+3 (8B fp16 load).

__global__ __launch_bounds__(256)
void agg_kernel(const float* __restrict__ bias, float* __restrict__ outopt, int n) {
    float4* out4 = outopt ? (float4*)outopt : (float4*)g_y;
    int gtid = blockIdx.x * blockDim.x + threadIdx.x;
    int node = gtid >> 5;
    int lane = threadIdx.x & 31;
    if (node >= n) return;

    float di  = g_dinv[node];
    int beg = g_off[node], end = g_off[node + 1];
    float4 acc = {0.f, 0.f, 0.f, 0.f};
    for (int e = beg; e < end; e++) {
        int j = g_csr[e];
        float dj = __ldg(&g_dinv[j]);
        uint2 pk = __ldg((const uint2*)(g_h + (size_t)j * FDIM + lane * 4));
        float2 p0 = __half22float2(*(const __half2*)&pk.x);
        float2 p1 = __half22float2(*(const __half2*)&pk.y);
        acc.x += dj * p0.x; acc.y += dj * p0.y;
        acc.z += dj * p1.x; acc.w += dj * p1.y;
    }
    uint2 hk = __ldg((const uint2*)(g_h + (size_t)node * FDIM + lane * 4));
    float2 h0 = __half22float2(*(const __half2*)&hk.x);
    float2 h1 = __half22float2(*(const __half2*)&hk.y);
    float4 bb = __ldg(((const float4*)bias) + lane);
    float4 o;
    o.x = di * (acc.x + di * h0.x) + bb.x;
    o.y = di * (acc.y + di * h0.y) + bb.y;
    o.z = di * (acc.z + di * h1.x) + bb.z;
    o.w = di * (acc.w + di * h1.y) + bb.w;
    o.x = o.x > 0.f ? o.x : 0.01f * o.x;
    o.y = o.y > 0.f ? o.y : 0.01f * o.y;
    o.z = o.z > 0.f ? o.z : 0.01f * o.z;
    o.w = o.w > 0.f ? o.w : 0.01f * o.w;
    out4[(size_t)node * 32 + lane] = o;
}

// ---------------- launch ----------------

extern "C" void kernel_launch(void* const* d_in, const int* in_sizes, int n_in,
                              void* d_out, int out_size) {
    const float* x  = (const float*)d_in[0];
    const void*  ei = d_in[1];
    const float* W1 = (const float*)d_in[2];
    const float* b1 = (const float*)d_in[3];
    const float* W2 = (const float*)d_in[4];
    const float* b2 = (const float*)d_in[5];
    float*       out = (float*)d_out;

    int N = in_sizes[0] / FDIM;        // 100000
    int E = in_sizes[1] / 2;           // 1600000

    int nB = (N + 255) / 256;
    int eB = (E + 255) / 256;
    int gemmB = (N + 127) / 128;
    int aggB  = (N * 32 + 255) / 256;

    cudaFuncSetAttribute(gemm_mma_kernel,
                         cudaFuncAttributeMaxDynamicSharedMemorySize, SM_TOT);

    // CSR build
    detect_kernel<<<1, 256>>>((const unsigned int*)ei);
    zero_kernel<<<nB, 256>>>(N);
    deg_kernel<<<eB, 256>>>(ei, E, N);
    dinv_kernel<<<nB, 256>>>(N);
    scan1_kernel<<<SCAN_NB, SCAN_B>>>(N);
    scan2_kernel<<<1, 1>>>(SCAN_NB, N, E);
    scan3_kernel<<<SCAN_NB, SCAN_B>>>(N);
    scatter_kernel<<<eB, 256>>>(ei, E, N);

    // layer 1: h = x@W1^T ; y = agg(h)+b1, lrelu
    gemm_mma_kernel<<<gemmB, 256, SM_TOT>>>(x, W1, N);
    agg_kernel<<<aggB, 256>>>(b1, nullptr, N);
    // layer 2: h = y@W2^T ; out = agg(h)+b2, lrelu
    gemm_mma_kernel<<<gemmB, 256, SM_TOT>>>(nullptr, W2, N);
    agg_kernel<<<aggB, 256>>>(b2, out, N);
}

// round 7
// speedup vs baseline: 1.2299x; 1.0236x over previous
#include <cuda_runtime.h>
#include <cuda_bf16.h>
#include <cuda_fp16.h>
#include <cstdint>

// ---------------------------------------------------------------------------
// GCN 2-layer encoder. CSR built per call (overlapped with layer-1 GEMM via
// capture fork-join); pull aggregation over fp16 h, 2 edges/warp-iteration;
// GEMM via mma.sync bf16 3-term split (fp32 accumulate).
// ---------------------------------------------------------------------------

#define N_NODES 100000
#define N_EDGES 1600000
#define FDIM    128
#define SCAN_B  1024
#define SCAN_NB ((N_NODES + SCAN_B - 1) / SCAN_B)   // 98

__device__ int    g_is64;
__device__ int    g_deg[N_NODES];
__device__ int    g_pos[N_NODES];
__device__ int    g_off[N_NODES + 1];
__device__ int    g_bsum[SCAN_NB];
__device__ float  g_dinv[N_NODES];
__device__ int    g_csr[N_EDGES];
__device__ __half g_h[(size_t)N_NODES * FDIM];   // GEMM output, fp16 (per layer)
__device__ float  g_y[(size_t)N_NODES * FDIM];   // layer-1 activation (fp32)

// ---------------- dtype detection (parallel) ----------------
__global__ void detect_kernel(const unsigned int* __restrict__ w) {
    int z = (w[2 * threadIdx.x + 1] == 0u) ? 1 : 0;
    int total = __syncthreads_count(z);
    if (threadIdx.x == 0) g_is64 = (total == 256) ? 1 : 0;
}

__device__ __forceinline__ int edge_at(const void* ei, long long idx, int n) {
    long long v = g_is64 ? ((const long long*)ei)[idx]
                         : (long long)((const int*)ei)[idx];
    int i = (int)v;
    if (i < 0) i = 0;
    if (i >= n) i = n - 1;
    return i;
}

// ---------------- CSR build ----------------

__global__ void zero_kernel(int n) {
    int i = blockIdx.x * blockDim.x + threadIdx.x;
    if (i < n) { g_deg[i] = 0; g_pos[i] = 0; }
}

__global__ void deg_kernel(const void* __restrict__ ei, int E, int n) {
    int e = blockIdx.x * blockDim.x + threadIdx.x;
    if (e < E) atomicAdd(&g_deg[edge_at(ei, (long long)E + e, n)], 1);
}

__global__ void dinv_kernel(int n) {
    int i = blockIdx.x * blockDim.x + threadIdx.x;
    if (i < n) g_dinv[i] = rsqrtf((float)g_deg[i] + 1.0f);
}

__global__ void scan1_kernel(int n) {
    __shared__ int s[SCAN_B];
    int t = threadIdx.x;
    int i = blockIdx.x * SCAN_B + t;
    int v = (i < n) ? g_deg[i] : 0;
    s[t] = v;
    __syncthreads();
    for (int o = 1; o < SCAN_B; o <<= 1) {
        int x = (t >= o) ? s[t - o] : 0;
        __syncthreads();
        s[t] += x;
        __syncthreads();
    }
    if (i < n) g_off[i] = s[t] - v;
    if (t == SCAN_B - 1) g_bsum[blockIdx.x] = s[t];
}

__global__ void scan2_kernel(int nb, int n, int E) {
    int run = 0;
    for (int b = 0; b < nb; b++) { int v = g_bsum[b]; g_bsum[b] = run; run += v; }
    g_off[n] = E;
}

__global__ void scan3_kernel(int n) {
    int i = blockIdx.x * SCAN_B + threadIdx.x;
    if (i < n) g_off[i] += g_bsum[blockIdx.x];
}

__global__ void scatter_kernel(const void* __restrict__ ei, int E, int n) {
    int e = blockIdx.x * blockDim.x + threadIdx.x;
    if (e < E) {
        int s = edge_at(ei, e, n);
        int d = edge_at(ei, (long long)E + e, n);
        int p = g_off[d] + atomicAdd(&g_pos[d], 1);
        g_csr[p] = s;
    }
}

// ---------------- mma.sync bf16x3 GEMM: g_h[M,128](fp16) = A[M,128] @ W^T --

#define TROWB 272
#define TSZ   (128 * TROWB)
#define AHI_O 0
#define ALO_O (TSZ)
#define WHI_O (2 * TSZ)
#define WLO_O (3 * TSZ)
#define SM_TOT (4 * TSZ)                 // 139264 B dynamic smem

__device__ __forceinline__ uint32_t smem_u32(const void* p) {
    uint32_t a;
    asm("{ .reg .u64 t; cvta.to.shared.u64 t, %1; cvt.u32.u64 %0, t; }"
        : "=r"(a) : "l"(p));
    return a;
}

__device__ __forceinline__ uint32_t pack_bf2(__nv_bfloat16 a, __nv_bfloat16 b) {
    return (uint32_t)__bfloat16_as_ushort(a) | ((uint32_t)__bfloat16_as_ushort(b) << 16);
}

__device__ __forceinline__ void cvt_store(char* smem, int hi_off, int lo_off,
                                          int r, int c4, float4 v) {
    __nv_bfloat16 h0 = __float2bfloat16_rn(v.x);
    __nv_bfloat16 h1 = __float2bfloat16_rn(v.y);
    __nv_bfloat16 h2 = __float2bfloat16_rn(v.z);
    __nv_bfloat16 h3 = __float2bfloat16_rn(v.w);
    __nv_bfloat16 l0 = __float2bfloat16_rn(v.x - __bfloat162float(h0));
    __nv_bfloat16 l1 = __float2bfloat16_rn(v.y - __bfloat162float(h1));
    __nv_bfloat16 l2 = __float2bfloat16_rn(v.z - __bfloat162float(h2));
    __nv_bfloat16 l3 = __float2bfloat16_rn(v.w - __bfloat162float(h3));
    int off = r * TROWB + c4 * 2;
    uint2 hp; hp.x = pack_bf2(h0, h1); hp.y = pack_bf2(h2, h3);
    uint2 lp; lp.x = pack_bf2(l0, l1); lp.y = pack_bf2(l2, l3);
    *(uint2*)(smem + hi_off + off) = hp;
    *(uint2*)(smem + lo_off + off) = lp;
}

__device__ __forceinline__ void ldm_x4(uint32_t* r, uint32_t addr) {
    asm volatile("ldmatrix.sync.aligned.m8n8.x4.shared.b16 {%0,%1,%2,%3}, [%4];"
                 : "=r"(r[0]), "=r"(r[1]), "=r"(r[2]), "=r"(r[3]) : "r"(addr));
}

__device__ __forceinline__ void mma_bf16(float* c, const uint32_t* a,
                                         uint32_t b0, uint32_t b1) {
    asm volatile(
        "mma.sync.aligned.m16n8k16.row.col.f32.bf16.bf16.f32 "
        "{%0,%1,%2,%3}, {%4,%5,%6,%7}, {%8,%9}, {%0,%1,%2,%3};"
        : "+f"(c[0]), "+f"(c[1]), "+f"(c[2]), "+f"(c[3])
        : "r"(a[0]), "r"(a[1]), "r"(a[2]), "r"(a[3]), "r"(b0), "r"(b1));
}

__global__ __launch_bounds__(256, 1)
void gemm_mma_kernel(const float* __restrict__ Aopt, const float* __restrict__ W,
                     int M) {
    extern __shared__ char smem[];
    const float* A = Aopt ? Aopt : g_y;
    int tid = threadIdx.x;
    int wid = tid >> 5;
    int lane = tid & 31;
    int row0 = blockIdx.x * 128;
    int trows = (row0 + 128 <= M) ? 128 : (M - row0);

    for (int idx = tid; idx < 128 * 32; idx += 256) {
        int r = idx >> 5;
        int c4 = (idx & 31) << 2;
        float4 v = {0.f, 0.f, 0.f, 0.f};
        if (r < trows) v = *(const float4*)(A + (size_t)(row0 + r) * FDIM + c4);
        cvt_store(smem, AHI_O, ALO_O, r, c4, v);
        float4 wv = *(const float4*)(W + (size_t)r * FDIM + c4);
        cvt_store(smem, WHI_O, WLO_O, r, c4, wv);
    }
    __syncthreads();

    uint32_t sbase = smem_u32(smem);
    int warpM = wid & 3;
    int warpN = wid >> 2;

    float acc[2][8][4];
#pragma unroll
    for (int mt = 0; mt < 2; mt++)
#pragma unroll
        for (int nt = 0; nt < 8; nt++)
#pragma unroll
            for (int q = 0; q < 4; q++) acc[mt][nt][q] = 0.f;

    uint32_t aoff = (uint32_t)((warpM * 32 + (lane & 15)) * TROWB + ((lane >> 4) * 8) * 2);
    int g = lane >> 3;
    uint32_t boff = (uint32_t)((warpN * 64 + (g >> 1) * 8 + (lane & 7)) * TROWB + (g & 1) * 16);

#pragma unroll
    for (int t = 0; t < 3; t++) {
        uint32_t abase = sbase + (t == 2 ? ALO_O : AHI_O) + aoff;
        uint32_t bbase = sbase + (t == 1 ? WLO_O : WHI_O) + boff;
#pragma unroll
        for (int ks = 0; ks < 8; ks++) {
            uint32_t af[2][4], bf[4][4];
            ldm_x4(af[0], abase + ks * 32);
            ldm_x4(af[1], abase + 16 * TROWB + ks * 32);
#pragma unroll
            for (int np = 0; np < 4; np++)
                ldm_x4(bf[np], bbase + np * 16 * TROWB + ks * 32);
#pragma unroll
            for (int mt = 0; mt < 2; mt++)
#pragma unroll
                for (int nt = 0; nt < 8; nt++)
                    mma_bf16(acc[mt][nt], af[mt],
                             bf[nt >> 1][(nt & 1) * 2], bf[nt >> 1][(nt & 1) * 2 + 1]);
        }
    }

    int crow = warpM * 32 + (lane >> 2);
    int ccol = warpN * 64 + (lane & 3) * 2;
#pragma unroll
    for (int mt = 0; mt < 2; mt++) {
#pragma unroll
        for (int nt = 0; nt < 8; nt++) {
            int r0 = row0 + crow + mt * 16;
            int c = ccol + nt * 8;
            if (r0 < M) {
                float2 v0 = {acc[mt][nt][0], acc[mt][nt][1]};
                *(__half2*)(g_h + (size_t)r0 * FDIM + c) = __float22half2_rn(v0);
            }
            if (r0 + 8 < M) {
                float2 v1 = {acc[mt][nt][2], acc[mt][nt][3]};
                *(__half2*)(g_h + (size_t)(r0 + 8) * FDIM + c) = __float22half2_rn(v1);
            }
        }
    }
}

// ---------------- Pull aggregation + bias + leaky_relu ----------------
// one warp per node; half-warps take even/odd edges (2 edges per iter).
// lane&15 covers 8 features via one uint4 (16B) fp16 load.

__device__ __forceinline__ void unpack8(uint4 pk, float* f) {
    float2 a = __half22float2(*(const __half2*)&pk.x);
    float2 b = __half22float2(*(const __half2*)&pk.y);
    float2 c = __half22float2(*(const __half2*)&pk.z);
    float2 d = __half22float2(*(const __half2*)&pk.w);
    f[0] = a.x; f[1] = a.y; f[2] = b.x; f[3] = b.y;
    f[4] = c.x; f[5] = c.y; f[6] = d.x; f[7] = d.y;
}

__global__ __launch_bounds__(256)
void agg_kernel(const float* __restrict__ bias, float* __restrict__ outopt, int n) {
    float* outp = outopt ? outopt : g_y;
    int gtid = blockIdx.x * blockDim.x + threadIdx.x;
    int node = gtid >> 5;
    int lane = threadIdx.x & 31;
    if (node >= n) return;
    int half = lane >> 4;
    int fl = lane & 15;                       // feature block: fl*8 .. fl*8+7

    float di  = g_dinv[node];
    int beg = g_off[node], end = g_off[node + 1];
    float acc[8] = {0.f, 0.f, 0.f, 0.f, 0.f, 0.f, 0.f, 0.f};
    for (int e = beg + half; e < end; e += 2) {
        int j = g_csr[e];
        float dj = __ldg(&g_dinv[j]);
        uint4 pk = __ldg((const uint4*)(g_h + (size_t)j * FDIM + fl * 8));
        float p[8]; unpack8(pk, p);
#pragma unroll
        for (int q = 0; q < 8; q++) acc[q] += dj * p[q];
    }
    // combine the two half-warps (same feature block, different edges)
#pragma unroll
    for (int q = 0; q < 8; q++) acc[q] += __shfl_xor_sync(0xffffffffu, acc[q], 16);

    uint4 hk = __ldg((const uint4*)(g_h + (size_t)node * FDIM + fl * 8));
    float hs[8]; unpack8(hk, hs);
    float4 bb0 = __ldg((const float4*)(bias + fl * 8));
    float4 bb1 = __ldg((const float4*)(bias + fl * 8 + 4));
    float bv[8] = {bb0.x, bb0.y, bb0.z, bb0.w, bb1.x, bb1.y, bb1.z, bb1.w};
    float o[8];
#pragma unroll
    for (int q = 0; q < 8; q++) {
        float v = di * (acc[q] + di * hs[q]) + bv[q];
        o[q] = v > 0.f ? v : 0.01f * v;
    }
    if (half == 0) {
        float4 s0 = {o[0], o[1], o[2], o[3]};
        float4 s1 = {o[4], o[5], o[6], o[7]};
        *(float4*)(outp + (size_t)node * FDIM + fl * 8)     = s0;
        *(float4*)(outp + (size_t)node * FDIM + fl * 8 + 4) = s1;
    }
}

// ---------------- launch ----------------

extern "C" void kernel_launch(void* const* d_in, const int* in_sizes, int n_in,
                              void* d_out, int out_size) {
    const float* x  = (const float*)d_in[0];
    const void*  ei = d_in[1];
    const float* W1 = (const float*)d_in[2];
    const float* b1 = (const float*)d_in[3];
    const float* W2 = (const float*)d_in[4];
    const float* b2 = (const float*)d_in[5];
    float*       out = (float*)d_out;

    int N = in_sizes[0] / FDIM;        // 100000
    int E = in_sizes[1] / 2;           // 1600000

    int nB = (N + 255) / 256;
    int eB = (E + 255) / 256;
    int gemmB = (N + 127) / 128;
    int aggB  = (N * 32 + 255) / 256;

    cudaFuncSetAttribute(gemm_mma_kernel,
                         cudaFuncAttributeMaxDynamicSharedMemorySize, SM_TOT);

    // side stream + fork/join events (host resources, created once; the
    // captured graph is identical on every call)
    static cudaStream_t s2;
    static cudaEvent_t evFork, evJoin;
    static bool init = false;
    if (!init) {
        cudaStreamCreateWithFlags(&s2, cudaStreamNonBlocking);
        cudaEventCreateWithFlags(&evFork, cudaEventDisableTiming);
        cudaEventCreateWithFlags(&evJoin, cudaEventDisableTiming);
        init = true;
    }

    // fork: CSR build on s2, layer-1 GEMM on main stream (independent work)
    cudaEventRecord(evFork, 0);
    cudaStreamWaitEvent(s2, evFork, 0);

    detect_kernel<<<1, 256, 0, s2>>>((const unsigned int*)ei);
    zero_kernel<<<nB, 256, 0, s2>>>(N);
    deg_kernel<<<eB, 256, 0, s2>>>(ei, E, N);
    dinv_kernel<<<nB, 256, 0, s2>>>(N);
    scan1_kernel<<<SCAN_NB, SCAN_B, 0, s2>>>(N);
    scan2_kernel<<<1, 1, 0, s2>>>(SCAN_NB, N, E);
    scan3_kernel<<<SCAN_NB, SCAN_B, 0, s2>>>(N);
    scatter_kernel<<<eB, 256, 0, s2>>>(ei, E, N);

    gemm_mma_kernel<<<gemmB, 256, SM_TOT>>>(x, W1, N);

    // join: aggregation needs both CSR and h
    cudaEventRecord(evJoin, s2);
    cudaStreamWaitEvent(0, evJoin, 0);

    agg_kernel<<<aggB, 256>>>(b1, nullptr, N);
    gemm_mma_kernel<<<gemmB, 256, SM_TOT>>>(nullptr, W2, N);
    agg_kernel<<<aggB, 256>>>(b2, out, N);
}

// round 8
// speedup vs baseline: 1.3452x; 1.0938x over previous
#include <cuda_runtime.h>
#include <cuda_bf16.h>
#include <cuda_fp16.h>
#include <cstdint>

// ---------------------------------------------------------------------------
// GCN 2-layer encoder. CSR built per call (overlapped with layer-1 GEMM);
// pull aggregation over fp16 h with software-pipelined edge loop; fp16
// inter-layer activation; GEMM via mma.sync bf16 3-term split, 512 threads.
// ---------------------------------------------------------------------------

#define N_NODES 100000
#define N_EDGES 1600000
#define FDIM    128
#define SCAN_B  1024
#define SCAN_NB ((N_NODES + SCAN_B - 1) / SCAN_B)   // 98

__device__ int    g_is64;
__device__ int    g_deg[N_NODES];
__device__ int    g_pos[N_NODES];
__device__ int    g_off[N_NODES + 1];
__device__ int    g_bsum[SCAN_NB];
__device__ float  g_dinv[N_NODES];
__device__ int    g_csr[N_EDGES];
__device__ __half g_h[(size_t)N_NODES * FDIM];    // GEMM output (per layer)
__device__ __half g_yh[(size_t)N_NODES * FDIM];   // layer-1 activation (fp16)

// ---------------- dtype detection (parallel) ----------------
__global__ void detect_kernel(const unsigned int* __restrict__ w) {
    int z = (w[2 * threadIdx.x + 1] == 0u) ? 1 : 0;
    int total = __syncthreads_count(z);
    if (threadIdx.x == 0) g_is64 = (total == 256) ? 1 : 0;
}

__device__ __forceinline__ int edge_at(const void* ei, long long idx, int n) {
    long long v = g_is64 ? ((const long long*)ei)[idx]
                         : (long long)((const int*)ei)[idx];
    int i = (int)v;
    if (i < 0) i = 0;
    if (i >= n) i = n - 1;
    return i;
}

// ---------------- CSR build ----------------

__global__ void zero_kernel(int n) {
    int i = blockIdx.x * blockDim.x + threadIdx.x;
    if (i < n) g_deg[i] = 0;
}

__global__ void deg_kernel(const void* __restrict__ ei, int E, int n) {
    int e = blockIdx.x * blockDim.x + threadIdx.x;
    if (e < E) atomicAdd(&g_deg[edge_at(ei, (long long)E + e, n)], 1);
}

__global__ void dinv_kernel(int n) {
    int i = blockIdx.x * blockDim.x + threadIdx.x;
    if (i < n) g_dinv[i] = rsqrtf((float)g_deg[i] + 1.0f);
}

__global__ void scan1_kernel(int n) {
    __shared__ int s[SCAN_B];
    int t = threadIdx.x;
    int i = blockIdx.x * SCAN_B + t;
    int v = (i < n) ? g_deg[i] : 0;
    s[t] = v;
    __syncthreads();
    for (int o = 1; o < SCAN_B; o <<= 1) {
        int x = (t >= o) ? s[t - o] : 0;
        __syncthreads();
        s[t] += x;
        __syncthreads();
    }
    if (i < n) g_off[i] = s[t] - v;
    if (t == SCAN_B - 1) g_bsum[blockIdx.x] = s[t];
}

__global__ void scan2_kernel(int nb, int n, int E) {
    int run = 0;
    for (int b = 0; b < nb; b++) { int v = g_bsum[b]; g_bsum[b] = run; run += v; }
    g_off[n] = E;
}

__global__ void scan3_kernel(int n) {
    int i = blockIdx.x * SCAN_B + threadIdx.x;
    if (i < n) {
        int o = g_off[i] + g_bsum[blockIdx.x];
        g_off[i] = o;
        g_pos[i] = o;                       // seed scatter cursor
    }
}

__global__ void scatter_kernel(const void* __restrict__ ei, int E, int n) {
    int e = blockIdx.x * blockDim.x + threadIdx.x;
    if (e < E) {
        int s = edge_at(ei, e, n);
        int d = edge_at(ei, (long long)E + e, n);
        g_csr[atomicAdd(&g_pos[d], 1)] = s;
    }
}

// ---------------- mma.sync bf16x3 GEMM: g_h[M,128](fp16) = A[M,128] @ W^T --
// A from fp32 (layer 1) or fp16 g_yh (layer 2). 512 threads, 16 warps,
// each warp a 32x32 C-tile. Rows padded to 272B: bank-conflict-free ldmatrix.

#define TROWB 272
#define TSZ   (128 * TROWB)
#define AHI_O 0
#define ALO_O (TSZ)
#define WHI_O (2 * TSZ)
#define WLO_O (3 * TSZ)
#define SM_TOT (4 * TSZ)                 // 139264 B dynamic smem

__device__ __forceinline__ uint32_t smem_u32(const void* p) {
    uint32_t a;
    asm("{ .reg .u64 t; cvta.to.shared.u64 t, %1; cvt.u32.u64 %0, t; }"
        : "=r"(a) : "l"(p));
    return a;
}

__device__ __forceinline__ uint32_t pack_bf2(__nv_bfloat16 a, __nv_bfloat16 b) {
    return (uint32_t)__bfloat16_as_ushort(a) | ((uint32_t)__bfloat16_as_ushort(b) << 16);
}

__device__ __forceinline__ void cvt_store(char* smem, int hi_off, int lo_off,
                                          int r, int c4, float4 v) {
    __nv_bfloat16 h0 = __float2bfloat16_rn(v.x);
    __nv_bfloat16 h1 = __float2bfloat16_rn(v.y);
    __nv_bfloat16 h2 = __float2bfloat16_rn(v.z);
    __nv_bfloat16 h3 = __float2bfloat16_rn(v.w);
    __nv_bfloat16 l0 = __float2bfloat16_rn(v.x - __bfloat162float(h0));
    __nv_bfloat16 l1 = __float2bfloat16_rn(v.y - __bfloat162float(h1));
    __nv_bfloat16 l2 = __float2bfloat16_rn(v.z - __bfloat162float(h2));
    __nv_bfloat16 l3 = __float2bfloat16_rn(v.w - __bfloat162float(h3));
    int off = r * TROWB + c4 * 2;
    uint2 hp; hp.x = pack_bf2(h0, h1); hp.y = pack_bf2(h2, h3);
    uint2 lp; lp.x = pack_bf2(l0, l1); lp.y = pack_bf2(l2, l3);
    *(uint2*)(smem + hi_off + off) = hp;
    *(uint2*)(smem + lo_off + off) = lp;
}

__device__ __forceinline__ void ldm_x4(uint32_t* r, uint32_t addr) {
    asm volatile("ldmatrix.sync.aligned.m8n8.x4.shared.b16 {%0,%1,%2,%3}, [%4];"
                 : "=r"(r[0]), "=r"(r[1]), "=r"(r[2]), "=r"(r[3]) : "r"(addr));
}

__device__ __forceinline__ void mma_bf16(float* c, const uint32_t* a,
                                         uint32_t b0, uint32_t b1) {
    asm volatile(
        "mma.sync.aligned.m16n8k16.row.col.f32.bf16.bf16.f32 "
        "{%0,%1,%2,%3}, {%4,%5,%6,%7}, {%8,%9}, {%0,%1,%2,%3};"
        : "+f"(c[0]), "+f"(c[1]), "+f"(c[2]), "+f"(c[3])
        : "r"(a[0]), "r"(a[1]), "r"(a[2]), "r"(a[3]), "r"(b0), "r"(b1));
}

__global__ __launch_bounds__(512, 1)
void gemm_mma_kernel(const float* __restrict__ Aopt, const float* __restrict__ W,
                     int M) {
    extern __shared__ char smem[];
    int tid = threadIdx.x;
    int wid = tid >> 5;
    int lane = tid & 31;
    int row0 = blockIdx.x * 128;
    int trows = (row0 + 128 <= M) ? 128 : (M - row0);

    // load + split-convert tiles (A fp32 path or fp16 g_yh path)
    for (int idx = tid; idx < 128 * 32; idx += 512) {
        int r = idx >> 5;
        int c4 = (idx & 31) << 2;
        float4 v = {0.f, 0.f, 0.f, 0.f};
        if (r < trows) {
            if (Aopt) {
                v = *(const float4*)(Aopt + (size_t)(row0 + r) * FDIM + c4);
            } else {
                uint2 pk = *(const uint2*)(g_yh + (size_t)(row0 + r) * FDIM + c4);
                float2 a = __half22float2(*(const __half2*)&pk.x);
                float2 b = __half22float2(*(const __half2*)&pk.y);
                v.x = a.x; v.y = a.y; v.z = b.x; v.w = b.y;
            }
        }
        cvt_store(smem, AHI_O, ALO_O, r, c4, v);
        float4 wv = *(const float4*)(W + (size_t)r * FDIM + c4);
        cvt_store(smem, WHI_O, WLO_O, r, c4, wv);
    }
    __syncthreads();

    uint32_t sbase = smem_u32(smem);
    int warpM = wid & 3;                 // 4 x 32 rows
    int warpN = wid >> 2;                // 4 x 32 cols

    float acc[2][4][4];
#pragma unroll
    for (int mt = 0; mt < 2; mt++)
#pragma unroll
        for (int nt = 0; nt < 4; nt++)
#pragma unroll
            for (int q = 0; q < 4; q++) acc[mt][nt][q] = 0.f;

    uint32_t aoff = (uint32_t)((warpM * 32 + (lane & 15)) * TROWB + ((lane >> 4) * 8) * 2);
    int g = lane >> 3;
    uint32_t boff = (uint32_t)((warpN * 32 + (g >> 1) * 8 + (lane & 7)) * TROWB + (g & 1) * 16);

#pragma unroll
    for (int t = 0; t < 3; t++) {
        uint32_t abase = sbase + (t == 2 ? ALO_O : AHI_O) + aoff;
        uint32_t bbase = sbase + (t == 1 ? WLO_O : WHI_O) + boff;
#pragma unroll
        for (int ks = 0; ks < 8; ks++) {
            uint32_t af[2][4], bf[2][4];
            ldm_x4(af[0], abase + ks * 32);
            ldm_x4(af[1], abase + 16 * TROWB + ks * 32);
#pragma unroll
            for (int np = 0; np < 2; np++)
                ldm_x4(bf[np], bbase + np * 16 * TROWB + ks * 32);
#pragma unroll
            for (int mt = 0; mt < 2; mt++)
#pragma unroll
                for (int nt = 0; nt < 4; nt++)
                    mma_bf16(acc[mt][nt], af[mt],
                             bf[nt >> 1][(nt & 1) * 2], bf[nt >> 1][(nt & 1) * 2 + 1]);
        }
    }

    // epilogue -> fp16 g_h
    int crow = warpM * 32 + (lane >> 2);
    int ccol = warpN * 32 + (lane & 3) * 2;
#pragma unroll
    for (int mt = 0; mt < 2; mt++) {
#pragma unroll
        for (int nt = 0; nt < 4; nt++) {
            int r0 = row0 + crow + mt * 16;
            int c = ccol + nt * 8;
            if (r0 < M) {
                float2 v0 = {acc[mt][nt][0], acc[mt][nt][1]};
                *(__half2*)(g_h + (size_t)r0 * FDIM + c) = __float22half2_rn(v0);
            }
            if (r0 + 8 < M) {
                float2 v1 = {acc[mt][nt][2], acc[mt][nt][3]};
                *(__half2*)(g_h + (size_t)(r0 + 8) * FDIM + c) = __float22half2_rn(v1);
            }
        }
    }
}

// ---------------- Pull aggregation + bias + leaky_relu ----------------
// one warp/node; half-warps take even/odd edges; lane&15 covers 8 features
// (one uint4 fp16 load). Edge loop software-pipelined (prefetch j, dinv).
// Output: fp16 g_yh (intermediate) or fp32 out (final).

__device__ __forceinline__ void unpack8(uint4 pk, float* f) {
    float2 a = __half22float2(*(const __half2*)&pk.x);
    float2 b = __half22float2(*(const __half2*)&pk.y);
    float2 c = __half22float2(*(const __half2*)&pk.z);
    float2 d = __half22float2(*(const __half2*)&pk.w);
    f[0] = a.x; f[1] = a.y; f[2] = b.x; f[3] = b.y;
    f[4] = c.x; f[5] = c.y; f[6] = d.x; f[7] = d.y;
}

__global__ __launch_bounds__(256)
void agg_kernel(const float* __restrict__ bias, float* __restrict__ outopt, int n) {
    int gtid = blockIdx.x * blockDim.x + threadIdx.x;
    int node = gtid >> 5;
    int lane = threadIdx.x & 31;
    if (node >= n) return;
    int half = lane >> 4;
    int fl = lane & 15;                       // feature block fl*8 .. fl*8+7

    float di  = g_dinv[node];
    int beg = g_off[node], end = g_off[node + 1];
    float acc[8] = {0.f, 0.f, 0.f, 0.f, 0.f, 0.f, 0.f, 0.f};

    int e = beg + half;
    int j = 0; float dj = 0.f;
    if (e < end) { j = g_csr[e]; dj = __ldg(&g_dinv[j]); }
    while (e < end) {
        int e2 = e + 2;
        int j2 = 0; float dj2 = 0.f;
        if (e2 < end) { j2 = g_csr[e2]; dj2 = __ldg(&g_dinv[j2]); }
        uint4 pk = __ldg((const uint4*)(g_h + (size_t)j * FDIM + fl * 8));
        float p[8]; unpack8(pk, p);
#pragma unroll
        for (int q = 0; q < 8; q++) acc[q] += dj * p[q];
        e = e2; j = j2; dj = dj2;
    }
#pragma unroll
    for (int q = 0; q < 8; q++) acc[q] += __shfl_xor_sync(0xffffffffu, acc[q], 16);

    uint4 hk = __ldg((const uint4*)(g_h + (size_t)node * FDIM + fl * 8));
    float hs[8]; unpack8(hk, hs);
    float4 bb0 = __ldg((const float4*)(bias + fl * 8));
    float4 bb1 = __ldg((const float4*)(bias + fl * 8 + 4));
    float bv[8] = {bb0.x, bb0.y, bb0.z, bb0.w, bb1.x, bb1.y, bb1.z, bb1.w};
    float o[8];
#pragma unroll
    for (int q = 0; q < 8; q++) {
        float v = di * (acc[q] + di * hs[q]) + bv[q];
        o[q] = v > 0.f ? v : 0.01f * v;
    }
    if (half == 0) {
        if (outopt) {
            float4 s0 = {o[0], o[1], o[2], o[3]};
            float4 s1 = {o[4], o[5], o[6], o[7]};
            *(float4*)(outopt + (size_t)node * FDIM + fl * 8)     = s0;
            *(float4*)(outopt + (size_t)node * FDIM + fl * 8 + 4) = s1;
        } else {
            uint4 s;
            float2 t0 = {o[0], o[1]}, t1 = {o[2], o[3]};
            float2 t2 = {o[4], o[5]}, t3 = {o[6], o[7]};
            __half2 q0 = __float22half2_rn(t0), q1 = __float22half2_rn(t1);
            __half2 q2 = __float22half2_rn(t2), q3 = __float22half2_rn(t3);
            s.x = *(uint32_t*)&q0; s.y = *(uint32_t*)&q1;
            s.z = *(uint32_t*)&q2; s.w = *(uint32_t*)&q3;
            *(uint4*)(g_yh + (size_t)node * FDIM + fl * 8) = s;
        }
    }
}

// ---------------- launch ----------------

extern "C" void kernel_launch(void* const* d_in, const int* in_sizes, int n_in,
                              void* d_out, int out_size) {
    const float* x  = (const float*)d_in[0];
    const void*  ei = d_in[1];
    const float* W1 = (const float*)d_in[2];
    const float* b1 = (const float*)d_in[3];
    const float* W2 = (const float*)d_in[4];
    const float* b2 = (const float*)d_in[5];
    float*       out = (float*)d_out;

    int N = in_sizes[0] / FDIM;        // 100000
    int E = in_sizes[1] / 2;           // 1600000

    int nB = (N + 255) / 256;
    int eB = (E + 255) / 256;
    int gemmB = (N + 127) / 128;
    int aggB  = (N * 32 + 255) / 256;

    cudaFuncSetAttribute(gemm_mma_kernel,
                         cudaFuncAttributeMaxDynamicSharedMemorySize, SM_TOT);

    static cudaStream_t s2;
    static cudaEvent_t evFork, evJoin;
    static bool init = false;
    if (!init) {
        cudaStreamCreateWithFlags(&s2, cudaStreamNonBlocking);
        cudaEventCreateWithFlags(&evFork, cudaEventDisableTiming);
        cudaEventCreateWithFlags(&evJoin, cudaEventDisableTiming);
        init = true;
    }

    // fork: CSR build on s2, layer-1 GEMM on main stream
    cudaEventRecord(evFork, 0);
    cudaStreamWaitEvent(s2, evFork, 0);

    detect_kernel<<<1, 256, 0, s2>>>((const unsigned int*)ei);
    zero_kernel<<<nB, 256, 0, s2>>>(N);
    deg_kernel<<<eB, 256, 0, s2>>>(ei, E, N);
    dinv_kernel<<<nB, 256, 0, s2>>>(N);
    scan1_kernel<<<SCAN_NB, SCAN_B, 0, s2>>>(N);
    scan2_kernel<<<1, 1, 0, s2>>>(SCAN_NB, N, E);
    scan3_kernel<<<SCAN_NB, SCAN_B, 0, s2>>>(N);
    scatter_kernel<<<eB, 256, 0, s2>>>(ei, E, N);

    gemm_mma_kernel<<<gemmB, 512, SM_TOT>>>(x, W1, N);

    // join: aggregation needs both CSR and h
    cudaEventRecord(evJoin, s2);
    cudaStreamWaitEvent(0, evJoin, 0);

    agg_kernel<<<aggB, 256>>>(b1, nullptr, N);          // -> fp16 g_yh
    gemm_mma_kernel<<<gemmB, 512, SM_TOT>>>(nullptr, W2, N);
    agg_kernel<<<aggB, 256>>>(b2, out, N);              // -> fp32 out
}

// round 9
// speedup vs baseline: 1.4584x; 1.0841x over previous
#include <cuda_runtime.h>
#include <cuda_bf16.h>
#include <cuda_fp16.h>
#include <cstdint>

// ---------------------------------------------------------------------------
// GCN 2-layer encoder. CSR built per call (overlapped with layer-1 GEMM);
// GEMM epilogue pre-scales rows by dinv so aggregation is a pure row-sum;
// fp16 h / inter-layer activation; GEMM via mma.sync bf16 3-term split.
// ---------------------------------------------------------------------------

#define N_NODES 100000
#define N_EDGES 1600000
#define FDIM    128
#define SCAN_B  1024
#define SCAN_NB ((N_NODES + SCAN_B - 1) / SCAN_B)   // 98

__device__ int    g_is64;
__device__ int    g_deg[N_NODES];
__device__ int    g_pos[N_NODES];
__device__ int    g_off[N_NODES + 1];
__device__ int    g_bsum[SCAN_NB];
__device__ float  g_dinv[N_NODES];
__device__ int    g_csr[N_EDGES];
__device__ __half g_h[(size_t)N_NODES * FDIM];    // dinv-scaled GEMM output
__device__ __half g_yh[(size_t)N_NODES * FDIM];   // layer-1 activation (fp16)

// ---------------- detect dtype + zero counters (fused) ----------------
__global__ void dz_kernel(const unsigned int* __restrict__ w, int n) {
    int i = blockIdx.x * blockDim.x + threadIdx.x;
    if (i < n) g_deg[i] = 0;
    if (blockIdx.x == 0) {
        int z = (w[2 * threadIdx.x + 1] == 0u) ? 1 : 0;
        int total = __syncthreads_count(z);
        if (threadIdx.x == 0) g_is64 = (total == 256) ? 1 : 0;
    }
}

__device__ __forceinline__ int edge_at(const void* ei, long long idx, int n) {
    long long v = g_is64 ? ((const long long*)ei)[idx]
                         : (long long)((const int*)ei)[idx];
    int i = (int)v;
    if (i < 0) i = 0;
    if (i >= n) i = n - 1;
    return i;
}

// ---------------- CSR build ----------------

__global__ void deg_kernel(const void* __restrict__ ei, int E, int n) {
    int e = blockIdx.x * blockDim.x + threadIdx.x;
    if (e < E) atomicAdd(&g_deg[edge_at(ei, (long long)E + e, n)], 1);
}

// per-block scan of counts + dinv computation (fused)
__global__ void scan1_kernel(int n) {
    __shared__ int s[SCAN_B];
    int t = threadIdx.x;
    int i = blockIdx.x * SCAN_B + t;
    int v = 0;
    if (i < n) {
        v = g_deg[i];
        g_dinv[i] = rsqrtf((float)v + 1.0f);
    }
    s[t] = v;
    __syncthreads();
    for (int o = 1; o < SCAN_B; o <<= 1) {
        int x = (t >= o) ? s[t - o] : 0;
        __syncthreads();
        s[t] += x;
        __syncthreads();
    }
    if (i < n) g_off[i] = s[t] - v;
    if (t == SCAN_B - 1) g_bsum[blockIdx.x] = s[t];
}

// parallel exclusive scan of the SCAN_NB block sums (one 128-thread block)
__global__ void scan2_kernel(int nb, int n, int E) {
    __shared__ int s[128];
    int t = threadIdx.x;
    int v = (t < nb) ? g_bsum[t] : 0;
    s[t] = v;
    __syncthreads();
    for (int o = 1; o < 128; o <<= 1) {
        int x = (t >= o) ? s[t - o] : 0;
        __syncthreads();
        s[t] += x;
        __syncthreads();
    }
    if (t < nb) g_bsum[t] = s[t] - v;       // exclusive
    if (t == 0) g_off[n] = E;
}

__global__ void scan3_kernel(int n) {
    int i = blockIdx.x * SCAN_B + threadIdx.x;
    if (i < n) {
        int o = g_off[i] + g_bsum[blockIdx.x];
        g_off[i] = o;
        g_pos[i] = o;                       // seed scatter cursor
    }
}

__global__ void scatter_kernel(const void* __restrict__ ei, int E, int n) {
    int e = blockIdx.x * blockDim.x + threadIdx.x;
    if (e < E) {
        int s = edge_at(ei, e, n);
        int d = edge_at(ei, (long long)E + e, n);
        g_csr[atomicAdd(&g_pos[d], 1)] = s;
    }
}

// ---------------- mma.sync bf16x3 GEMM -------------------------------------
// g_h[M,128](fp16) = dinv[:,None] * (A[M,128] @ W^T). A fp32 or fp16 g_yh.
// 512 threads, 16 warps, 32x32 C-tile each. 272B rows: conflict-free ldmatrix.

#define TROWB 272
#define TSZ   (128 * TROWB)
#define AHI_O 0
#define ALO_O (TSZ)
#define WHI_O (2 * TSZ)
#define WLO_O (3 * TSZ)
#define SM_TOT (4 * TSZ)                 // 139264 B dynamic smem

__device__ __forceinline__ uint32_t smem_u32(const void* p) {
    uint32_t a;
    asm("{ .reg .u64 t; cvta.to.shared.u64 t, %1; cvt.u32.u64 %0, t; }"
        : "=r"(a) : "l"(p));
    return a;
}

__device__ __forceinline__ uint32_t pack_bf2(__nv_bfloat16 a, __nv_bfloat16 b) {
    return (uint32_t)__bfloat16_as_ushort(a) | ((uint32_t)__bfloat16_as_ushort(b) << 16);
}

__device__ __forceinline__ void cvt_store(char* smem, int hi_off, int lo_off,
                                          int r, int c4, float4 v) {
    __nv_bfloat16 h0 = __float2bfloat16_rn(v.x);
    __nv_bfloat16 h1 = __float2bfloat16_rn(v.y);
    __nv_bfloat16 h2 = __float2bfloat16_rn(v.z);
    __nv_bfloat16 h3 = __float2bfloat16_rn(v.w);
    __nv_bfloat16 l0 = __float2bfloat16_rn(v.x - __bfloat162float(h0));
    __nv_bfloat16 l1 = __float2bfloat16_rn(v.y - __bfloat162float(h1));
    __nv_bfloat16 l2 = __float2bfloat16_rn(v.z - __bfloat162float(h2));
    __nv_bfloat16 l3 = __float2bfloat16_rn(v.w - __bfloat162float(h3));
    int off = r * TROWB + c4 * 2;
    uint2 hp; hp.x = pack_bf2(h0, h1); hp.y = pack_bf2(h2, h3);
    uint2 lp; lp.x = pack_bf2(l0, l1); lp.y = pack_bf2(l2, l3);
    *(uint2*)(smem + hi_off + off) = hp;
    *(uint2*)(smem + lo_off + off) = lp;
}

__device__ __forceinline__ void ldm_x4(uint32_t* r, uint32_t addr) {
    asm volatile("ldmatrix.sync.aligned.m8n8.x4.shared.b16 {%0,%1,%2,%3}, [%4];"
                 : "=r"(r[0]), "=r"(r[1]), "=r"(r[2]), "=r"(r[3]) : "r"(addr));
}

__device__ __forceinline__ void mma_bf16(float* c, const uint32_t* a,
                                         uint32_t b0, uint32_t b1) {
    asm volatile(
        "mma.sync.aligned.m16n8k16.row.col.f32.bf16.bf16.f32 "
        "{%0,%1,%2,%3}, {%4,%5,%6,%7}, {%8,%9}, {%0,%1,%2,%3};"
        : "+f"(c[0]), "+f"(c[1]), "+f"(c[2]), "+f"(c[3])
        : "r"(a[0]), "r"(a[1]), "r"(a[2]), "r"(a[3]), "r"(b0), "r"(b1));
}

__global__ __launch_bounds__(512, 1)
void gemm_mma_kernel(const float* __restrict__ Aopt, const float* __restrict__ W,
                     int M) {
    extern __shared__ char smem[];
    int tid = threadIdx.x;
    int wid = tid >> 5;
    int lane = tid & 31;
    int row0 = blockIdx.x * 128;
    int trows = (row0 + 128 <= M) ? 128 : (M - row0);

    for (int idx = tid; idx < 128 * 32; idx += 512) {
        int r = idx >> 5;
        int c4 = (idx & 31) << 2;
        float4 v = {0.f, 0.f, 0.f, 0.f};
        if (r < trows) {
            if (Aopt) {
                v = *(const float4*)(Aopt + (size_t)(row0 + r) * FDIM + c4);
            } else {
                uint2 pk = *(const uint2*)(g_yh + (size_t)(row0 + r) * FDIM + c4);
                float2 a = __half22float2(*(const __half2*)&pk.x);
                float2 b = __half22float2(*(const __half2*)&pk.y);
                v.x = a.x; v.y = a.y; v.z = b.x; v.w = b.y;
            }
        }
        cvt_store(smem, AHI_O, ALO_O, r, c4, v);
        float4 wv = *(const float4*)(W + (size_t)r * FDIM + c4);
        cvt_store(smem, WHI_O, WLO_O, r, c4, wv);
    }
    __syncthreads();

    uint32_t sbase = smem_u32(smem);
    int warpM = wid & 3;
    int warpN = wid >> 2;

    float acc[2][4][4];
#pragma unroll
    for (int mt = 0; mt < 2; mt++)
#pragma unroll
        for (int nt = 0; nt < 4; nt++)
#pragma unroll
            for (int q = 0; q < 4; q++) acc[mt][nt][q] = 0.f;

    uint32_t aoff = (uint32_t)((warpM * 32 + (lane & 15)) * TROWB + ((lane >> 4) * 8) * 2);
    int g = lane >> 3;
    uint32_t boff = (uint32_t)((warpN * 32 + (g >> 1) * 8 + (lane & 7)) * TROWB + (g & 1) * 16);

#pragma unroll
    for (int t = 0; t < 3; t++) {
        uint32_t abase = sbase + (t == 2 ? ALO_O : AHI_O) + aoff;
        uint32_t bbase = sbase + (t == 1 ? WLO_O : WHI_O) + boff;
#pragma unroll
        for (int ks = 0; ks < 8; ks++) {
            uint32_t af[2][4], bf[2][4];
            ldm_x4(af[0], abase + ks * 32);
            ldm_x4(af[1], abase + 16 * TROWB + ks * 32);
#pragma unroll
            for (int np = 0; np < 2; np++)
                ldm_x4(bf[np], bbase + np * 16 * TROWB + ks * 32);
#pragma unroll
            for (int mt = 0; mt < 2; mt++)
#pragma unroll
                for (int nt = 0; nt < 4; nt++)
                    mma_bf16(acc[mt][nt], af[mt],
                             bf[nt >> 1][(nt & 1) * 2], bf[nt >> 1][(nt & 1) * 2 + 1]);
        }
    }

    // epilogue: scale rows by dinv, store fp16 g_h
    int crow = warpM * 32 + (lane >> 2);
    int ccol = warpN * 32 + (lane & 3) * 2;
#pragma unroll
    for (int mt = 0; mt < 2; mt++) {
        int r0 = row0 + crow + mt * 16;
        float d0 = (r0 < M)     ? __ldg(&g_dinv[r0])     : 0.f;
        float d1 = (r0 + 8 < M) ? __ldg(&g_dinv[r0 + 8]) : 0.f;
#pragma unroll
        for (int nt = 0; nt < 4; nt++) {
            int c = ccol + nt * 8;
            if (r0 < M) {
                float2 v0 = {d0 * acc[mt][nt][0], d0 * acc[mt][nt][1]};
                *(__half2*)(g_h + (size_t)r0 * FDIM + c) = __float22half2_rn(v0);
            }
            if (r0 + 8 < M) {
                float2 v1 = {d1 * acc[mt][nt][2], d1 * acc[mt][nt][3]};
                *(__half2*)(g_h + (size_t)(r0 + 8) * FDIM + c) = __float22half2_rn(v1);
            }
        }
    }
}

// ---------------- Pull aggregation + bias + leaky_relu ----------------
// out_i = di * (sum_j h'_j) + di * h'_i + b  with h' = dinv-scaled rows.
// one warp/node; half-warps take even/odd edges; lane&15 covers 8 features.

__device__ __forceinline__ void unpack8(uint4 pk, float* f) {
    float2 a = __half22float2(*(const __half2*)&pk.x);
    float2 b = __half22float2(*(const __half2*)&pk.y);
    float2 c = __half22float2(*(const __half2*)&pk.z);
    float2 d = __half22float2(*(const __half2*)&pk.w);
    f[0] = a.x; f[1] = a.y; f[2] = b.x; f[3] = b.y;
    f[4] = c.x; f[5] = c.y; f[6] = d.x; f[7] = d.y;
}

__global__ __launch_bounds__(256)
void agg_kernel(const float* __restrict__ bias, float* __restrict__ outopt, int n) {
    int gtid = blockIdx.x * blockDim.x + threadIdx.x;
    int node = gtid >> 5;
    int lane = threadIdx.x & 31;
    if (node >= n) return;
    int half = lane >> 4;
    int fl = lane & 15;

    float di  = g_dinv[node];
    int beg = g_off[node], end = g_off[node + 1];
    float acc[8] = {0.f, 0.f, 0.f, 0.f, 0.f, 0.f, 0.f, 0.f};

    int e = beg + half;
    int j = (e < end) ? g_csr[e] : 0;
    while (e < end) {
        int e2 = e + 2;
        int j2 = (e2 < end) ? g_csr[e2] : 0;
        uint4 pk = __ldg((const uint4*)(g_h + (size_t)j * FDIM + fl * 8));
        float p[8]; unpack8(pk, p);
#pragma unroll
        for (int q = 0; q < 8; q++) acc[q] += p[q];
        e = e2; j = j2;
    }
#pragma unroll
    for (int q = 0; q < 8; q++) acc[q] += __shfl_xor_sync(0xffffffffu, acc[q], 16);

    uint4 hk = __ldg((const uint4*)(g_h + (size_t)node * FDIM + fl * 8));
    float hs[8]; unpack8(hk, hs);
    float4 bb0 = __ldg((const float4*)(bias + fl * 8));
    float4 bb1 = __ldg((const float4*)(bias + fl * 8 + 4));
    float bv[8] = {bb0.x, bb0.y, bb0.z, bb0.w, bb1.x, bb1.y, bb1.z, bb1.w};
    float o[8];
#pragma unroll
    for (int q = 0; q < 8; q++) {
        float v = di * (acc[q] + hs[q]) + bv[q];
        o[q] = v > 0.f ? v : 0.01f * v;
    }
    if (half == 0) {
        if (outopt) {
            float4 s0 = {o[0], o[1], o[2], o[3]};
            float4 s1 = {o[4], o[5], o[6], o[7]};
            *(float4*)(outopt + (size_t)node * FDIM + fl * 8)     = s0;
            *(float4*)(outopt + (size_t)node * FDIM + fl * 8 + 4) = s1;
        } else {
            uint4 s;
            float2 t0 = {o[0], o[1]}, t1 = {o[2], o[3]};
            float2 t2 = {o[4], o[5]}, t3 = {o[6], o[7]};
            __half2 q0 = __float22half2_rn(t0), q1 = __float22half2_rn(t1);
            __half2 q2 = __float22half2_rn(t2), q3 = __float22half2_rn(t3);
            s.x = *(uint32_t*)&q0; s.y = *(uint32_t*)&q1;
            s.z = *(uint32_t*)&q2; s.w = *(uint32_t*)&q3;
            *(uint4*)(g_yh + (size_t)node * FDIM + fl * 8) = s;
        }
    }
}

// ---------------- launch ----------------

extern "C" void kernel_launch(void* const* d_in, const int* in_sizes, int n_in,
                              void* d_out, int out_size) {
    const float* x  = (const float*)d_in[0];
    const void*  ei = d_in[1];
    const float* W1 = (const float*)d_in[2];
    const float* b1 = (const float*)d_in[3];
    const float* W2 = (const float*)d_in[4];
    const float* b2 = (const float*)d_in[5];
    float*       out = (float*)d_out;

    int N = in_sizes[0] / FDIM;        // 100000
    int E = in_sizes[1] / 2;           // 1600000

    int nB = (N + 255) / 256;
    int eB = (E + 255) / 256;
    int gemmB = (N + 127) / 128;
    int aggB  = (N * 32 + 255) / 256;

    cudaFuncSetAttribute(gemm_mma_kernel,
                         cudaFuncAttributeMaxDynamicSharedMemorySize, SM_TOT);

    static cudaStream_t s2;
    static cudaEvent_t evFork, evDinv, evJoin;
    static bool init = false;
    if (!init) {
        cudaStreamCreateWithFlags(&s2, cudaStreamNonBlocking);
        cudaEventCreateWithFlags(&evFork, cudaEventDisableTiming);
        cudaEventCreateWithFlags(&evDinv, cudaEventDisableTiming);
        cudaEventCreateWithFlags(&evJoin, cudaEventDisableTiming);
        init = true;
    }

    // fork: CSR chain on s2
    cudaEventRecord(evFork, 0);
    cudaStreamWaitEvent(s2, evFork, 0);

    dz_kernel<<<nB, 256, 0, s2>>>((const unsigned int*)ei, N);
    deg_kernel<<<eB, 256, 0, s2>>>(ei, E, N);
    scan1_kernel<<<SCAN_NB, SCAN_B, 0, s2>>>(N);      // also computes dinv
    cudaEventRecord(evDinv, s2);                      // dinv ready
    scan2_kernel<<<1, 128, 0, s2>>>(SCAN_NB, N, E);
    scan3_kernel<<<SCAN_NB, SCAN_B, 0, s2>>>(N);
    scatter_kernel<<<eB, 256, 0, s2>>>(ei, E, N);
    cudaEventRecord(evJoin, s2);

    // main: GEMM1 (needs dinv for epilogue) overlaps scan2/scan3/scatter
    cudaStreamWaitEvent(0, evDinv, 0);
    gemm_mma_kernel<<<gemmB, 512, SM_TOT>>>(x, W1, N);

    cudaStreamWaitEvent(0, evJoin, 0);
    agg_kernel<<<aggB, 256>>>(b1, nullptr, N);          // -> fp16 g_yh
    gemm_mma_kernel<<<gemmB, 512, SM_TOT>>>(nullptr, W2, N);
    agg_kernel<<<aggB, 256>>>(b2, out, N);              // -> fp32 out
}